// round 11
// baseline (speedup 1.0000x reference)
#include <cuda_runtime.h>
#include <cuda_fp16.h>
#include <cstdint>
#include <cstddef>

#define ALPHA 0.2f
#define L2E   1.4426950408889634f

static constexpr int BB = 4;
static constexpr int NN = 4096;
static constexpr int CC = 64;
static constexpr int NSPLIT = 2;                 // j-splits

// ---------------------------------------------------------------------------
// Scratch (__device__ globals: allocation-free rule)
// ---------------------------------------------------------------------------
__device__ __half    g_hT [BB * CC * NN];        // [b][f][n]  fp16 h^T
__device__ float     g_f1 [BB * NN];             // f1[b][n]
__device__ float     g_f2t[NN * BB];             // f2 transposed: [n][b]
__device__ float     g_m  [BB * NN];             // MASKED row max of e (post-leaky)
__device__ uint32_t  g_adjbits[NN * 128];        // adj rows bit-packed
__device__ __half    g_pC [NSPLIT * BB * NN * CC];  // fp16 partial PV per split
__device__ float     g_prs[NSPLIT * BB * NN];       // partial row sums

__device__ __forceinline__ uint32_t smem_u32(const void* p) {
    uint32_t a;
    asm("{ .reg .u64 t; cvta.to.shared.u64 t, %1; cvt.u32.u64 %0, t; }"
        : "=r"(a) : "l"(p));
    return a;
}

// pack two f32 -> f16x2 (first arg in LOW half)
__device__ __forceinline__ uint32_t pack_h2(float lo, float hi) {
    uint32_t d;
    asm("cvt.rn.f16x2.f32 %0, %1, %2;" : "=r"(d) : "f"(hi), "f"(lo));
    return d;
}

__device__ __forceinline__ void mma_f16(float c[4], uint32_t a0, uint32_t a1,
                                        uint32_t a2, uint32_t a3,
                                        uint32_t b0, uint32_t b1) {
    asm volatile(
        "mma.sync.aligned.m16n8k16.row.col.f32.f16.f16.f32 "
        "{%0,%1,%2,%3}, {%4,%5,%6,%7}, {%8,%9}, {%0,%1,%2,%3};"
        : "+f"(c[0]), "+f"(c[1]), "+f"(c[2]), "+f"(c[3])
        : "r"(a0), "r"(a1), "r"(a2), "r"(a3), "r"(b0), "r"(b1));
}

// ---------------------------------------------------------------------------
// Kernel 1: h = x@W ; f1 = h.a1 ; f2 = h.a2 ; h^T stored fp16 [b][f][n].
// ---------------------------------------------------------------------------
__global__ __launch_bounds__(256) void k_proj(const float* __restrict__ x,
                                              const float* __restrict__ W,
                                              const float* __restrict__ a)
{
    __shared__ float Ws[64][64];
    __shared__ float xs[16][64];
    __shared__ float hsm[64][17];
    __shared__ float red1[8][4], red2[8][4];

    int tid  = threadIdx.x;
    int row0 = blockIdx.x * 16;
    int bb   = row0 >> 12;
    int n0   = row0 & (NN - 1);

#pragma unroll
    for (int t = 0; t < 16; t++) {
        int idx = tid + t * 256;
        Ws[idx >> 6][idx & 63] = W[idx];
    }
#pragma unroll
    for (int t = 0; t < 4; t++) {
        int idx = tid + t * 256;
        xs[idx >> 6][idx & 63] = x[(size_t)row0 * CC + idx];
    }
    __syncthreads();

    int slot = tid >> 6, f = tid & 63, w = tid >> 5;
    float a1v = a[f], a2v = a[64 + f];

#pragma unroll
    for (int rr = 0; rr < 4; ++rr) {
        int r = slot * 4 + rr;
        float hv = 0.f;
#pragma unroll
        for (int k = 0; k < 64; k++) hv = fmaf(xs[r][k], Ws[k][f], hv);
        hsm[f][r] = hv;

        float v1 = hv * a1v, v2 = hv * a2v;
#pragma unroll
        for (int off = 16; off; off >>= 1) {
            v1 += __shfl_down_sync(0xffffffffu, v1, off);
            v2 += __shfl_down_sync(0xffffffffu, v2, off);
        }
        if ((tid & 31) == 0) { red1[w][rr] = v1; red2[w][rr] = v2; }
    }
    __syncthreads();

#pragma unroll
    for (int t = 0; t < 2; t++) {
        int idx = tid + t * 256;            // 0..511
        int ff = idx >> 3, p = idx & 7;
        float v0 = hsm[ff][2 * p], v1 = hsm[ff][2 * p + 1];
        size_t base = ((size_t)(bb * CC + ff)) * NN + n0 + 2 * p;
        *(uint32_t*)(g_hT + base) = pack_h2(v0, v1);
    }

    if (tid < 16) {
        int s = tid & 3, rr = tid >> 2;
        int g = row0 + s * 4 + rr;
        g_f1[g] = red1[2 * s][rr] + red1[2 * s + 1][rr];
        float v2 = red2[2 * s][rr] + red2[2 * s + 1][rr];
        g_f2t[(g & (NN - 1)) * 4 + (g >> 12)] = v2;
    }
}

// ---------------------------------------------------------------------------
// Kernel 2 (v2): 16 rows per CTA. f2t cached ONCE in dynamic SMEM (64KB),
// adjacency streamed via coalesced LDG (single DRAM pass), ballot-packing
// fused. Kills the 256MB L2 re-read of the old per-row design.
// ---------------------------------------------------------------------------
__global__ __launch_bounds__(256) void k_rowmax(const int* __restrict__ adj)
{
    extern __shared__ float sf2[];               // [4096][4] = 64KB
    __shared__ float wred[16][8][BB];

    const int tid = threadIdx.x, wid = tid >> 5, lane = tid & 31;
    const int i0 = blockIdx.x * 16;

    // load f2t into SMEM (4096 float4)
#pragma unroll
    for (int t = 0; t < 16; t++) {
        int idx = tid + t * 256;
        ((float4*)sf2)[idx] = ((const float4*)g_f2t)[idx];
    }
    __syncthreads();

    for (int r = 0; r < 16; ++r) {
        const int i = i0 + r;
        const int* __restrict__ row = adj + ((size_t)i << 12);
        float M0 = -3.0e38f, M1 = -3.0e38f, M2v = -3.0e38f, M3 = -3.0e38f;
#pragma unroll 4
        for (int t = 0; t < 16; ++t) {
            int j  = t * 256 + tid;
            int av = row[j];                     // coalesced LDG
            unsigned bal = __ballot_sync(0xffffffffu, av > 0);
            if (lane == 0) g_adjbits[(size_t)i * 128 + t * 8 + wid] = bal;
            float4 f2 = ((const float4*)sf2)[j];
            M0  = fmaxf(M0,  (av > 0) ? f2.x : -3.0e38f);
            M1  = fmaxf(M1,  (av > 0) ? f2.y : -3.0e38f);
            M2v = fmaxf(M2v, (av > 0) ? f2.z : -3.0e38f);
            M3  = fmaxf(M3,  (av > 0) ? f2.w : -3.0e38f);
        }
#pragma unroll
        for (int off = 16; off; off >>= 1) {
            M0  = fmaxf(M0,  __shfl_xor_sync(0xffffffffu, M0,  off));
            M1  = fmaxf(M1,  __shfl_xor_sync(0xffffffffu, M1,  off));
            M2v = fmaxf(M2v, __shfl_xor_sync(0xffffffffu, M2v, off));
            M3  = fmaxf(M3,  __shfl_xor_sync(0xffffffffu, M3,  off));
        }
        if (lane == 0) {
            wred[r][wid][0] = M0;  wred[r][wid][1] = M1;
            wred[r][wid][2] = M2v; wred[r][wid][3] = M3;
        }
    }
    __syncthreads();
    if (tid < 64) {
        int r = tid >> 2, b = tid & 3;
        float m2 = wred[r][0][b];
#pragma unroll
        for (int w = 1; w < 8; w++) m2 = fmaxf(m2, wred[r][w][b]);
        int i = i0 + r;
        float z = g_f1[b * NN + i] + m2;
        g_m[b * NN + i] = fmaxf(z, ALPHA * z);   // masked leaky max
    }
}

// ---------------------------------------------------------------------------
// Kernel 3: partial PV via fp16 mma.sync. 64 i-rows x 2048 j per CTA
// (j split over gridDim.z=2). 128 threads (4 warps x 16 rows).
// ---------------------------------------------------------------------------
static constexpr int TJ     = 128;
static constexpr int JSEG   = NN / NSPLIT;        // 2048
static constexpr int NCH    = JSEG / TJ;          // 16 chunks per CTA
static constexpr int BPITCH = 272;                // 128 fp16 + 16B pad
static constexpr int BPLANE = 64 * BPITCH;        // 17408 B per buffer

__global__ __launch_bounds__(128) void k_pv()
{
    __shared__ __align__(16) char bsm[2 * BPLANE];
    __shared__ float f2s[2][TJ];

    const int tid = threadIdx.x, wid = tid >> 5, lane = tid & 31;
    const int g = lane >> 2, tg = lane & 3;
    const int b = blockIdx.y, i0 = blockIdx.x * 64;
    const int half = blockIdx.z;
    const int jbase = half * JSEG;
    const int gi0 = i0 + wid * 16 + g, gi1 = gi0 + 8;

    const float f1L0 = g_f1[b * NN + gi0] * L2E;
    const float mL0  = g_m [b * NN + gi0] * L2E;
    const float f1L1 = g_f1[b * NN + gi1] * L2E;
    const float mL1  = g_m [b * NN + gi1] * L2E;

    const uint4* bp0 = (const uint4*)(g_adjbits + (size_t)gi0 * 128 + half * 64);
    const uint4* bp1 = (const uint4*)(g_adjbits + (size_t)gi1 * 128 + half * 64);

    const uint32_t sbase  = smem_u32(bsm);
    const uint32_t f2base = smem_u32(f2s);

    auto stage = [&](int c, int buf) {
        const int jc = jbase + c * TJ;
#pragma unroll
        for (int t = 0; t < 8; t++) {
            int k = (tid << 3) + t;              // 0..1023 chunks of 16B
            int rr = k >> 4, q = k & 15;
            const __half* src = g_hT + (size_t)(b * CC + rr) * NN + jc + q * 8;
            uint32_t dst = sbase + buf * BPLANE + rr * BPITCH + q * 16;
            asm volatile("cp.async.cg.shared.global [%0], [%1], 16;"
                         :: "r"(dst), "l"(src));
        }
        {
            const float* src = g_f2t + (jc + tid) * 4 + b;
            uint32_t dst = f2base + (buf * TJ + tid) * 4;
            asm volatile("cp.async.ca.shared.global [%0], [%1], 4;"
                         :: "r"(dst), "l"(src));
        }
    };

    float C[8][4];
#pragma unroll
    for (int n = 0; n < 8; n++)
#pragma unroll
        for (int k = 0; k < 4; k++) C[n][k] = 0.f;
    float rs0 = 0.f, rs1 = 0.f;

    stage(0, 0);
    asm volatile("cp.async.commit_group;" ::: "memory");
    uint4 bits0 = bp0[0], bits1 = bp1[0];

    for (int c = 0; c < NCH; ++c) {
        const int buf = c & 1;
        if (c < NCH - 1) stage(c + 1, buf ^ 1);
        asm volatile("cp.async.commit_group;" ::: "memory");
        uint4 nb0 = bits0, nb1 = bits1;
        if (c < NCH - 1) { nb0 = bp0[c + 1]; nb1 = bp1[c + 1]; }
        asm volatile("cp.async.wait_group 1;" ::: "memory");
        __syncthreads();

        const char*  bb_ = bsm + buf * BPLANE;
        const float* f2p = f2s[buf];

#pragma unroll
        for (int ks = 0; ks < 8; ++ks) {
            const uint32_t w0 = (ks < 2) ? bits0.x : (ks < 4) ? bits0.y
                              : (ks < 6) ? bits0.z : bits0.w;
            const uint32_t w1 = (ks < 2) ? bits1.x : (ks < 4) ? bits1.y
                              : (ks < 6) ? bits1.z : bits1.w;
            const int sh = 2 * tg + 16 * (ks & 1);
            const uint32_t s0 = w0 >> sh;
            const uint32_t s1 = w1 >> sh;
            const int c0 = 2 * tg + 16 * ks;
            const float f2a = f2p[c0],     f2b = f2p[c0 + 1];
            const float f2c = f2p[c0 + 8], f2d = f2p[c0 + 9];

            float z, l, e;
#define PVAL(F1L, ML, F2) \
    (z = fmaf((F2), L2E, (F1L)), l = fmaxf(z, ALPHA * z) - (ML), \
     ({ asm("ex2.approx.f32 %0, %1;" : "=f"(e) : "f"(l)); e; }))
            float p00 = (s0 & 1u)     ? PVAL(f1L0, mL0, f2a) : 0.f;
            float p01 = (s0 & 2u)     ? PVAL(f1L0, mL0, f2b) : 0.f;
            float p02 = (s0 & 0x100u) ? PVAL(f1L0, mL0, f2c) : 0.f;
            float p03 = (s0 & 0x200u) ? PVAL(f1L0, mL0, f2d) : 0.f;
            float p10 = (s1 & 1u)     ? PVAL(f1L1, mL1, f2a) : 0.f;
            float p11 = (s1 & 2u)     ? PVAL(f1L1, mL1, f2b) : 0.f;
            float p12 = (s1 & 0x100u) ? PVAL(f1L1, mL1, f2c) : 0.f;
            float p13 = (s1 & 0x200u) ? PVAL(f1L1, mL1, f2d) : 0.f;
#undef PVAL

            rs0 += (p00 + p01) + (p02 + p03);
            rs1 += (p10 + p11) + (p12 + p13);

            uint32_t a0 = pack_h2(p00, p01);
            uint32_t a1 = pack_h2(p10, p11);
            uint32_t a2 = pack_h2(p02, p03);
            uint32_t a3 = pack_h2(p12, p13);

#pragma unroll
            for (int n0 = 0; n0 < 8; ++n0) {
                const uint32_t* rh =
                    (const uint32_t*)(bb_ + (n0 * 8 + g) * BPITCH);
                uint32_t b0 = rh[tg + 8 * ks];
                uint32_t b1 = rh[tg + 8 * ks + 4];
                mma_f16(C[n0], a0, a1, a2, a3, b0, b1);
            }
        }
        __syncthreads();
        bits0 = nb0; bits1 = nb1;
    }

    // ---- partial row sums: quad reduce over tg lanes ----
    rs0 += __shfl_xor_sync(0xffffffffu, rs0, 1);
    rs0 += __shfl_xor_sync(0xffffffffu, rs0, 2);
    rs1 += __shfl_xor_sync(0xffffffffu, rs1, 1);
    rs1 += __shfl_xor_sync(0xffffffffu, rs1, 2);
    if (tg == 0) {
        g_prs[(size_t)(half * BB + b) * NN + gi0] = rs0;
        g_prs[(size_t)(half * BB + b) * NN + gi1] = rs1;
    }

    // ---- store unnormalized partial C as fp16 ----
    __half* o0 = g_pC + ((size_t)(half * BB + b) * NN + gi0) * CC + 2 * tg;
    __half* o1 = g_pC + ((size_t)(half * BB + b) * NN + gi1) * CC + 2 * tg;
#pragma unroll
    for (int n0 = 0; n0 < 8; ++n0) {
        *(uint32_t*)(o0 + n0 * 8) = pack_h2(C[n0][0], C[n0][1]);
        *(uint32_t*)(o1 + n0 * 8) = pack_h2(C[n0][2], C[n0][3]);
    }
}

// ---------------------------------------------------------------------------
// Kernel 4: combine splits: out = relu(sum_q C_q / sum_q rs_q)
// ---------------------------------------------------------------------------
__global__ __launch_bounds__(256) void k_reduce(float* __restrict__ out)
{
    int e = blockIdx.x * 256 + threadIdx.x;   // quad index, 262144 total
    int row = e >> 4;                          // b*NN + n
    float s = g_prs[row] + g_prs[BB * NN + row];
    float inv = 1.0f / s;
    uint2 q0 = ((const uint2*)g_pC)[e];
    uint2 q1 = ((const uint2*)(g_pC + (size_t)BB * NN * CC))[e];
    float2 a0 = __half22float2(*(__half2*)&q0.x);
    float2 a1 = __half22float2(*(__half2*)&q0.y);
    float2 b0 = __half22float2(*(__half2*)&q1.x);
    float2 b1 = __half22float2(*(__half2*)&q1.y);
    float4 v;
    v.x = fmaxf((a0.x + b0.x) * inv, 0.f);
    v.y = fmaxf((a0.y + b0.y) * inv, 0.f);
    v.z = fmaxf((a1.x + b1.x) * inv, 0.f);
    v.w = fmaxf((a1.y + b1.y) * inv, 0.f);
    ((float4*)out)[e] = v;
}

// ---------------------------------------------------------------------------
extern "C" void kernel_launch(void* const* d_in, const int* in_sizes, int n_in,
                              void* d_out, int out_size)
{
    const float* x   = (const float*)d_in[0];   // [4,4096,64] f32
    const int*   adj = (const int*)  d_in[1];   // [4096,4096] i32
    const float* W   = (const float*)d_in[2];   // [64,64] f32
    const float* a   = (const float*)d_in[3];   // [128,1] f32
    float*       out = (float*)d_out;           // [4,4096,64] f32

    k_proj<<<BB * NN / 16, 256>>>(x, W, a);

    cudaFuncSetAttribute(k_rowmax, cudaFuncAttributeMaxDynamicSharedMemorySize,
                         NN * BB * (int)sizeof(float));
    k_rowmax<<<NN / 16, 256, NN * BB * sizeof(float)>>>(adj);

    dim3 grid(NN / 64, BB, NSPLIT);
    k_pv<<<grid, 128>>>();
    k_reduce<<<BB * NN * CC / 4 / 256, 256>>>(out);
}

// round 12
// speedup vs baseline: 1.0995x; 1.0995x over previous
#include <cuda_runtime.h>
#include <cuda_fp16.h>
#include <cstdint>
#include <cstddef>

#define ALPHA 0.2f
#define L2E   1.4426950408889634f

static constexpr int BB = 4;
static constexpr int NN = 4096;
static constexpr int CC = 64;
static constexpr int NSPLIT = 2;                 // j-splits

// ---------------------------------------------------------------------------
// Scratch (__device__ globals: allocation-free rule)
// ---------------------------------------------------------------------------
__device__ __half    g_hT [BB * CC * NN];        // [b][f][n]  fp16 h^T
__device__ float     g_f1 [BB * NN];             // f1[b][n]
__device__ float     g_f2t[NN * BB];             // f2 transposed: [n][b]
__device__ uint32_t  g_adjbits[NN * 128];        // adj rows bit-packed
__device__ __half    g_pC [NSPLIT * BB * NN * CC];  // fp16 partial PV per split
__device__ float     g_prs[NSPLIT * BB * NN];       // partial row sums
__device__ float     g_pm [NSPLIT * BB * NN];       // local row max (log2 dom.)

__device__ __forceinline__ uint32_t smem_u32(const void* p) {
    uint32_t a;
    asm("{ .reg .u64 t; cvta.to.shared.u64 t, %1; cvt.u32.u64 %0, t; }"
        : "=r"(a) : "l"(p));
    return a;
}

// pack two f32 -> f16x2 (first arg in LOW half)
__device__ __forceinline__ uint32_t pack_h2(float lo, float hi) {
    uint32_t d;
    asm("cvt.rn.f16x2.f32 %0, %1, %2;" : "=r"(d) : "f"(hi), "f"(lo));
    return d;
}

__device__ __forceinline__ void mma_f16(float c[4], uint32_t a0, uint32_t a1,
                                        uint32_t a2, uint32_t a3,
                                        uint32_t b0, uint32_t b1) {
    asm volatile(
        "mma.sync.aligned.m16n8k16.row.col.f32.f16.f16.f32 "
        "{%0,%1,%2,%3}, {%4,%5,%6,%7}, {%8,%9}, {%0,%1,%2,%3};"
        : "+f"(c[0]), "+f"(c[1]), "+f"(c[2]), "+f"(c[3])
        : "r"(a0), "r"(a1), "r"(a2), "r"(a3), "r"(b0), "r"(b1));
}

// ---------------------------------------------------------------------------
// Kernel 1: h = x@W ; f1 = h.a1 ; f2 = h.a2 ; h^T stored fp16 [b][f][n].
// 32 rows per CTA (W SMEM load amortized 2x vs R11).
// ---------------------------------------------------------------------------
__global__ __launch_bounds__(256) void k_proj(const float* __restrict__ x,
                                              const float* __restrict__ W,
                                              const float* __restrict__ a)
{
    __shared__ float Ws[64][64];
    __shared__ float xs[32][64];
    __shared__ float hsm[64][17];
    __shared__ float red1[8][4], red2[8][4];

    int tid  = threadIdx.x;
    int row0 = blockIdx.x * 32;
    int bb   = row0 >> 12;
    int n0b  = row0 & (NN - 1);

#pragma unroll
    for (int t = 0; t < 16; t++) {
        int idx = tid + t * 256;
        Ws[idx >> 6][idx & 63] = W[idx];
    }
#pragma unroll
    for (int t = 0; t < 8; t++) {
        int idx = tid + t * 256;
        xs[idx >> 6][idx & 63] = x[(size_t)row0 * CC + idx];
    }
    __syncthreads();

    int slot = tid >> 6, f = tid & 63, w = tid >> 5;
    float a1v = a[f], a2v = a[64 + f];

    for (int blk = 0; blk < 2; ++blk) {
#pragma unroll
        for (int rr = 0; rr < 4; ++rr) {
            int rl = slot * 4 + rr;              // local row in blk (0..15)
            int r  = blk * 16 + rl;              // row in xs
            float hv = 0.f;
#pragma unroll
            for (int k = 0; k < 64; k++) hv = fmaf(xs[r][k], Ws[k][f], hv);
            hsm[f][rl] = hv;

            float v1 = hv * a1v, v2 = hv * a2v;
#pragma unroll
            for (int off = 16; off; off >>= 1) {
                v1 += __shfl_down_sync(0xffffffffu, v1, off);
                v2 += __shfl_down_sync(0xffffffffu, v2, off);
            }
            if ((tid & 31) == 0) { red1[w][rr] = v1; red2[w][rr] = v2; }
        }
        __syncthreads();

        // transposed fp16 write for this blk: 512 pairs, 2 per thread
#pragma unroll
        for (int t = 0; t < 2; t++) {
            int idx = tid + t * 256;             // 0..511
            int ff = idx >> 3, p = idx & 7;
            float v0 = hsm[ff][2 * p], v1 = hsm[ff][2 * p + 1];
            size_t base = ((size_t)(bb * CC + ff)) * NN + n0b + blk * 16 + 2 * p;
            *(uint32_t*)(g_hT + base) = pack_h2(v0, v1);
        }
        if (tid < 16) {
            int s = tid & 3, rr = tid >> 2;
            int gg = row0 + blk * 16 + s * 4 + rr;
            g_f1[gg] = red1[2 * s][rr] + red1[2 * s + 1][rr];
            float v2 = red2[2 * s][rr] + red2[2 * s + 1][rr];
            g_f2t[(gg & (NN - 1)) * 4 + (gg >> 12)] = v2;
        }
        __syncthreads();                          // before hsm/red reuse
    }
}

// ---------------------------------------------------------------------------
// Kernel 2: adjacency bit-packing only (single coalesced DRAM pass).
// ---------------------------------------------------------------------------
__global__ __launch_bounds__(256) void k_pack(const int* __restrict__ adj)
{
    int i = blockIdx.x, tid = threadIdx.x;
    int wid = tid >> 5, lane = tid & 31;
    const int* __restrict__ row = adj + ((size_t)i << 12);
#pragma unroll
    for (int t = 0; t < 16; t++) {
        int j = wid * 512 + t * 32 + lane;
        unsigned bal = __ballot_sync(0xffffffffu, row[j] > 0);
        if (lane == 0) g_adjbits[(size_t)i * 128 + wid * 16 + t] = bal;
    }
}

// ---------------------------------------------------------------------------
// Kernel 3: partial PV via fp16 mma.sync + in-kernel LOCAL masked row max.
// 64 i-rows x 2048 j per CTA (gridDim.z=2 splits). 128 threads.
// ---------------------------------------------------------------------------
static constexpr int TJ     = 128;
static constexpr int JSEG   = NN / NSPLIT;        // 2048
static constexpr int NCH    = JSEG / TJ;          // 16 chunks per CTA
static constexpr int BPITCH = 272;                // 128 fp16 + 16B pad
static constexpr int BPLANE = 64 * BPITCH;        // 17408 B per buffer

__global__ __launch_bounds__(128) void k_pv()
{
    __shared__ __align__(16) char bsm[2 * BPLANE];
    __shared__ float f2s[2][TJ];

    const int tid = threadIdx.x, wid = tid >> 5, lane = tid & 31;
    const int g = lane >> 2, tg = lane & 3;
    const int b = blockIdx.y, i0 = blockIdx.x * 64;
    const int half = blockIdx.z;
    const int jbase = half * JSEG;
    const int gi0 = i0 + wid * 16 + g, gi1 = gi0 + 8;

    // ----------- prologue: local masked row max over this split -----------
    // Bits for the CTA's 64 rows x 64 words staged into bsm (scratch reuse).
    {
        uint4* sb4 = (uint4*)bsm;
#pragma unroll
        for (int t = 0; t < 8; t++) {
            int idx = tid + t * 128;             // 0..1023
            int r = idx >> 4, q = idx & 15;
            sb4[idx] = *(const uint4*)(g_adjbits + (size_t)(i0 + r) * 128
                                       + half * 64 + q * 4);
        }
    }
    __syncthreads();

    float M[16];
#pragma unroll
    for (int r = 0; r < 16; r++) M[r] = -3.0e38f;
    {
        const uint32_t* sb = (const uint32_t*)bsm;  // sb[r*64 + w]
        for (int tr = 0; tr < 4; ++tr) {
            float rf2[16];
#pragma unroll
            for (int t = 0; t < 16; t++) {
                int j = jbase + (tr * 16 + t) * 32 + lane;
                rf2[t] = g_f2t[j * 4 + b];
            }
#pragma unroll
            for (int r = 0; r < 16; r++) {
                const uint32_t* rw = sb + (wid * 16 + r) * 64 + tr * 16;
#pragma unroll
                for (int t = 0; t < 16; t++) {
                    uint32_t bit = (rw[t] >> lane) & 1u;
                    M[r] = fmaxf(M[r], bit ? rf2[t] : -3.0e38f);
                }
            }
        }
    }
#pragma unroll
    for (int r = 0; r < 16; r++) {
#pragma unroll
        for (int off = 16; off; off >>= 1)
            M[r] = fmaxf(M[r], __shfl_xor_sync(0xffffffffu, M[r], off));
    }
    const float f1r0 = g_f1[b * NN + gi0];
    const float f1r1 = g_f1[b * NN + gi1];
    float z0 = f1r0 + M[g];
    float z1 = f1r1 + M[g + 8];
    const float mL0 = fmaxf(z0, ALPHA * z0) * L2E;   // local max, log2 domain
    const float mL1 = fmaxf(z1, ALPHA * z1) * L2E;
    const float f1L0 = f1r0 * L2E;
    const float f1L1 = f1r1 * L2E;
    __syncthreads();                              // bits read done; bsm free

    // --------------------------- main loop --------------------------------
    const uint4* bp0 = (const uint4*)(g_adjbits + (size_t)gi0 * 128 + half * 64);
    const uint4* bp1 = (const uint4*)(g_adjbits + (size_t)gi1 * 128 + half * 64);

    const uint32_t sbase  = smem_u32(bsm);
    const uint32_t f2base = smem_u32(f2s);

    auto stage = [&](int c, int buf) {
        const int jc = jbase + c * TJ;
#pragma unroll
        for (int t = 0; t < 8; t++) {
            int k = (tid << 3) + t;              // 0..1023 chunks of 16B
            int rr = k >> 4, q = k & 15;
            const __half* src = g_hT + (size_t)(b * CC + rr) * NN + jc + q * 8;
            uint32_t dst = sbase + buf * BPLANE + rr * BPITCH + q * 16;
            asm volatile("cp.async.cg.shared.global [%0], [%1], 16;"
                         :: "r"(dst), "l"(src));
        }
        {
            const float* src = g_f2t + (jc + tid) * 4 + b;
            uint32_t dst = f2base + (buf * TJ + tid) * 4;
            asm volatile("cp.async.ca.shared.global [%0], [%1], 4;"
                         :: "r"(dst), "l"(src));
        }
    };

    float C[8][4];
#pragma unroll
    for (int n = 0; n < 8; n++)
#pragma unroll
        for (int k = 0; k < 4; k++) C[n][k] = 0.f;
    float rs0 = 0.f, rs1 = 0.f;

    stage(0, 0);
    asm volatile("cp.async.commit_group;" ::: "memory");
    uint4 bits0 = bp0[0], bits1 = bp1[0];

    for (int c = 0; c < NCH; ++c) {
        const int buf = c & 1;
        if (c < NCH - 1) stage(c + 1, buf ^ 1);
        asm volatile("cp.async.commit_group;" ::: "memory");
        uint4 nb0 = bits0, nb1 = bits1;
        if (c < NCH - 1) { nb0 = bp0[c + 1]; nb1 = bp1[c + 1]; }
        asm volatile("cp.async.wait_group 1;" ::: "memory");
        __syncthreads();

        const char*  bb_ = bsm + buf * BPLANE;
        const float* f2p = f2s[buf];

#pragma unroll
        for (int ks = 0; ks < 8; ++ks) {
            const uint32_t w0 = (ks < 2) ? bits0.x : (ks < 4) ? bits0.y
                              : (ks < 6) ? bits0.z : bits0.w;
            const uint32_t w1 = (ks < 2) ? bits1.x : (ks < 4) ? bits1.y
                              : (ks < 6) ? bits1.z : bits1.w;
            const int sh = 2 * tg + 16 * (ks & 1);
            const uint32_t s0 = w0 >> sh;
            const uint32_t s1 = w1 >> sh;
            const int c0 = 2 * tg + 16 * ks;
            const float f2a = f2p[c0],     f2b = f2p[c0 + 1];
            const float f2c = f2p[c0 + 8], f2d = f2p[c0 + 9];

            float z, l, e;
#define PVAL(F1L, ML, F2) \
    (z = fmaf((F2), L2E, (F1L)), l = fmaxf(z, ALPHA * z) - (ML), \
     ({ asm("ex2.approx.f32 %0, %1;" : "=f"(e) : "f"(l)); e; }))
            float p00 = (s0 & 1u)     ? PVAL(f1L0, mL0, f2a) : 0.f;
            float p01 = (s0 & 2u)     ? PVAL(f1L0, mL0, f2b) : 0.f;
            float p02 = (s0 & 0x100u) ? PVAL(f1L0, mL0, f2c) : 0.f;
            float p03 = (s0 & 0x200u) ? PVAL(f1L0, mL0, f2d) : 0.f;
            float p10 = (s1 & 1u)     ? PVAL(f1L1, mL1, f2a) : 0.f;
            float p11 = (s1 & 2u)     ? PVAL(f1L1, mL1, f2b) : 0.f;
            float p12 = (s1 & 0x100u) ? PVAL(f1L1, mL1, f2c) : 0.f;
            float p13 = (s1 & 0x200u) ? PVAL(f1L1, mL1, f2d) : 0.f;
#undef PVAL

            rs0 += (p00 + p01) + (p02 + p03);
            rs1 += (p10 + p11) + (p12 + p13);

            uint32_t a0 = pack_h2(p00, p01);
            uint32_t a1 = pack_h2(p10, p11);
            uint32_t a2 = pack_h2(p02, p03);
            uint32_t a3 = pack_h2(p12, p13);

#pragma unroll
            for (int n0 = 0; n0 < 8; ++n0) {
                const uint32_t* rh =
                    (const uint32_t*)(bb_ + (n0 * 8 + g) * BPITCH);
                uint32_t b0 = rh[tg + 8 * ks];
                uint32_t b1 = rh[tg + 8 * ks + 4];
                mma_f16(C[n0], a0, a1, a2, a3, b0, b1);
            }
        }
        __syncthreads();
        bits0 = nb0; bits1 = nb1;
    }

    // ---- partial row sums: quad reduce over tg lanes ----
    rs0 += __shfl_xor_sync(0xffffffffu, rs0, 1);
    rs0 += __shfl_xor_sync(0xffffffffu, rs0, 2);
    rs1 += __shfl_xor_sync(0xffffffffu, rs1, 1);
    rs1 += __shfl_xor_sync(0xffffffffu, rs1, 2);
    if (tg == 0) {
        size_t base = (size_t)(half * BB + b) * NN;
        g_prs[base + gi0] = rs0;
        g_prs[base + gi1] = rs1;
        g_pm [base + gi0] = mL0;
        g_pm [base + gi1] = mL1;
    }

    // ---- store unnormalized partial C as fp16 ----
    __half* o0 = g_pC + ((size_t)(half * BB + b) * NN + gi0) * CC + 2 * tg;
    __half* o1 = g_pC + ((size_t)(half * BB + b) * NN + gi1) * CC + 2 * tg;
#pragma unroll
    for (int n0 = 0; n0 < 8; ++n0) {
        *(uint32_t*)(o0 + n0 * 8) = pack_h2(C[n0][0], C[n0][1]);
        *(uint32_t*)(o1 + n0 * 8) = pack_h2(C[n0][2], C[n0][3]);
    }
}

// ---------------------------------------------------------------------------
// Kernel 4: combine splits with max-rescale:
// out = relu( (C0*w0 + C1*w1) / (s0*w0 + s1*w1) ),  w_q = 2^(m_q - m*)
// ---------------------------------------------------------------------------
__global__ __launch_bounds__(256) void k_reduce(float* __restrict__ out)
{
    int e = blockIdx.x * 256 + threadIdx.x;   // quad index, 262144 total
    int row = e >> 4;                          // b*NN + n
    float m0 = g_pm[row], m1 = g_pm[BB * NN + row];
    float ms = fmaxf(m0, m1);
    float w0 = exp2f(m0 - ms), w1 = exp2f(m1 - ms);
    float s  = g_prs[row] * w0 + g_prs[BB * NN + row] * w1;
    float inv = 1.0f / s;
    uint2 q0 = ((const uint2*)g_pC)[e];
    uint2 q1 = ((const uint2*)(g_pC + (size_t)BB * NN * CC))[e];
    float2 a0 = __half22float2(*(__half2*)&q0.x);
    float2 a1 = __half22float2(*(__half2*)&q0.y);
    float2 b0 = __half22float2(*(__half2*)&q1.x);
    float2 b1 = __half22float2(*(__half2*)&q1.y);
    float4 v;
    v.x = fmaxf((a0.x * w0 + b0.x * w1) * inv, 0.f);
    v.y = fmaxf((a0.y * w0 + b0.y * w1) * inv, 0.f);
    v.z = fmaxf((a1.x * w0 + b1.x * w1) * inv, 0.f);
    v.w = fmaxf((a1.y * w0 + b1.y * w1) * inv, 0.f);
    ((float4*)out)[e] = v;
}

// ---------------------------------------------------------------------------
extern "C" void kernel_launch(void* const* d_in, const int* in_sizes, int n_in,
                              void* d_out, int out_size)
{
    const float* x   = (const float*)d_in[0];   // [4,4096,64] f32
    const int*   adj = (const int*)  d_in[1];   // [4096,4096] i32
    const float* W   = (const float*)d_in[2];   // [64,64] f32
    const float* a   = (const float*)d_in[3];   // [128,1] f32
    float*       out = (float*)d_out;           // [4,4096,64] f32

    k_proj<<<BB * NN / 32, 256>>>(x, W, a);
    k_pack<<<NN, 256>>>(adj);
    dim3 grid(NN / 64, BB, NSPLIT);
    k_pv<<<grid, 128>>>();
    k_reduce<<<BB * NN * CC / 4 / 256, 256>>>(out);
}